// round 1
// baseline (speedup 1.0000x reference)
#include <cuda_runtime.h>
#include <math.h>

#define NE 8
#define NT 4096
#define ND 1024
#define NH 4096
#define SLOTS (2*NT + 64)

// ---------------- scratch (device globals; no allocation allowed) -----------
__device__ int   g_topi[NT*2];
__device__ float g_topw[NT*2];
__device__ int   g_cnt[NE];
__device__ float g_psum[NE];
__device__ int   g_off[NE+1];
__device__ int   g_cur[NE];
__device__ int   g_list[SLOTS];
__device__ int   g_slot[NT*2];
__device__ float g_H[(size_t)SLOTS*NH];   // ~135 MB
__device__ float g_Y[(size_t)SLOTS*ND];   // ~34 MB

// ---------------- init: reset per-launch counters ---------------------------
__global__ void k_init() {
    int i = threadIdx.x;
    if (i < NE) { g_cnt[i] = 0; g_psum[i] = 0.f; g_cur[i] = 0; }
}

// ---------------- router: logits, softmax, top-2, aux accumulators ----------
__global__ __launch_bounds__(256) void k_router(const float* __restrict__ x,
                                                const float* __restrict__ Wg) {
    __shared__ float sW[NE * ND];     // 32 KB
    int tid = threadIdx.x;
    for (int i = tid; i < NE * ND; i += 256) sW[i] = Wg[i];
    __syncthreads();

    int warp = tid >> 5, lane = tid & 31;
    int t = blockIdx.x * 8 + warp;

    float acc[NE];
#pragma unroll
    for (int e = 0; e < NE; e++) acc[e] = 0.f;
    const float* xr = x + (size_t)t * ND;
    for (int d = lane; d < ND; d += 32) {
        float xv = xr[d];
#pragma unroll
        for (int e = 0; e < NE; e++) acc[e] = fmaf(xv, sW[e * ND + d], acc[e]);
    }
#pragma unroll
    for (int e = 0; e < NE; e++) {
#pragma unroll
        for (int off = 16; off; off >>= 1)
            acc[e] += __shfl_xor_sync(0xffffffffu, acc[e], off);
    }

    if (lane == 0) {
        float mx = acc[0];
#pragma unroll
        for (int e = 1; e < NE; e++) mx = fmaxf(mx, acc[e]);
        float p[NE], Z = 0.f;
#pragma unroll
        for (int e = 0; e < NE; e++) { p[e] = expf(acc[e] - mx); Z += p[e]; }
        float inv = 1.f / Z;
#pragma unroll
        for (int e = 0; e < NE; e++) { p[e] *= inv; atomicAdd(&g_psum[e], p[e]); }

        // top-2, lowest-index tie-break (matches jax.lax.top_k)
        int i0 = 0;
#pragma unroll
        for (int e = 1; e < NE; e++) if (p[e] > p[i0]) i0 = e;
        int i1 = (i0 == 0) ? 1 : 0;
#pragma unroll
        for (int e = 0; e < NE; e++) if (e != i0 && p[e] > p[i1]) i1 = e;

        float s = p[i0] + p[i1];
        g_topi[t * 2 + 0] = i0;  g_topi[t * 2 + 1] = i1;
        g_topw[t * 2 + 0] = p[i0] / s;  g_topw[t * 2 + 1] = p[i1] / s;
        atomicAdd(&g_cnt[i0], 1);
        atomicAdd(&g_cnt[i1], 1);
    }
}

// ---------------- scan: offsets + aux loss ----------------------------------
__global__ void k_scan(float* __restrict__ out, int out_size) {
    if (threadIdx.x == 0 && blockIdx.x == 0) {
        int off = 0;
        for (int e = 0; e < NE; e++) { g_off[e] = off; off += g_cnt[e]; }
        g_off[NE] = off;
        float invT = 1.f / (float)NT;
        float aux = 0.f;
        for (int e = 0; e < NE; e++)
            aux += ((float)g_cnt[e] * invT) * (g_psum[e] * invT);
        aux *= (float)NE;
        if (out_size > NT * ND) out[(size_t)NT * ND] = aux;
    }
}

// ---------------- fill: scatter tokens into compact per-expert slot lists ---
__global__ void k_fill() {
    int t = blockIdx.x * blockDim.x + threadIdx.x;
    if (t >= NT) return;
#pragma unroll
    for (int k = 0; k < 2; k++) {
        int e = g_topi[t * 2 + k];
        int pos = atomicAdd(&g_cur[e], 1);
        int s = g_off[e] + pos;
        g_list[s] = t;
        g_slot[t * 2 + k] = s;
    }
}

// ---------------- GEMM1: H = silu(gather(x) @ W1[e] + b1[e]) ----------------
__global__ __launch_bounds__(256) void k_gemm1(const float* __restrict__ x,
                                               const float* __restrict__ W1,
                                               const float* __restrict__ b1) {
    int e = blockIdx.z;
    int ne = g_cnt[e];
    int mt = blockIdx.x;
    if (mt * 64 >= ne) return;
    int row0  = g_off[e] + mt * 64;
    int valid = ne - mt * 64; if (valid > 64) valid = 64;
    int n0 = blockIdx.y * 64;

    __shared__ float As[16][64];
    __shared__ float Bs[16][64];

    int tid = threadIdx.x;
    int lm = tid >> 2, lk = (tid & 3) * 4;     // A-tile loader: row, k-quad
    int bk = tid >> 4, bn = (tid & 15) * 4;    // B-tile loader
    int ty = (tid >> 4) * 4, tx = (tid & 15) * 4;

    const float* W1e = W1 + (size_t)e * ND * NH;
    long xoff = -1;
    if (lm < valid) xoff = (long)g_list[row0 + lm] * ND + lk;

    float acc[4][4];
#pragma unroll
    for (int i = 0; i < 4; i++)
#pragma unroll
        for (int j = 0; j < 4; j++) acc[i][j] = 0.f;

    for (int k0 = 0; k0 < ND; k0 += 16) {
        float4 av = make_float4(0.f, 0.f, 0.f, 0.f);
        if (xoff >= 0) av = *(const float4*)(x + xoff + k0);
        As[lk + 0][lm] = av.x; As[lk + 1][lm] = av.y;
        As[lk + 2][lm] = av.z; As[lk + 3][lm] = av.w;
        *(float4*)&Bs[bk][bn] =
            *(const float4*)(W1e + (size_t)(k0 + bk) * NH + n0 + bn);
        __syncthreads();
#pragma unroll
        for (int k = 0; k < 16; k++) {
            float4 a = *(const float4*)&As[k][ty];
            float4 b = *(const float4*)&Bs[k][tx];
            float a4[4] = {a.x, a.y, a.z, a.w};
            float b4[4] = {b.x, b.y, b.z, b.w};
#pragma unroll
            for (int i = 0; i < 4; i++)
#pragma unroll
                for (int j = 0; j < 4; j++)
                    acc[i][j] = fmaf(a4[i], b4[j], acc[i][j]);
        }
        __syncthreads();
    }

#pragma unroll
    for (int i = 0; i < 4; i++) {
        if (ty + i < valid) {
            size_t row = (size_t)(row0 + ty + i);
#pragma unroll
            for (int j = 0; j < 4; j++) {
                int col = n0 + tx + j;
                float z = acc[i][j] + b1[e * NH + col];
                g_H[row * NH + col] = z / (1.f + expf(-z));
            }
        }
    }
}

// ---------------- GEMM2: Y = H @ W2[e] + b2[e] -------------------------------
__global__ __launch_bounds__(256) void k_gemm2(const float* __restrict__ W2,
                                               const float* __restrict__ b2) {
    int e = blockIdx.z;
    int ne = g_cnt[e];
    int mt = blockIdx.x;
    if (mt * 64 >= ne) return;
    int row0  = g_off[e] + mt * 64;
    int valid = ne - mt * 64; if (valid > 64) valid = 64;
    int n0 = blockIdx.y * 64;

    __shared__ float As[16][64];
    __shared__ float Bs[16][64];

    int tid = threadIdx.x;
    int lm = tid >> 2, lk = (tid & 3) * 4;
    int bk = tid >> 4, bn = (tid & 15) * 4;
    int ty = (tid >> 4) * 4, tx = (tid & 15) * 4;

    const float* W2e = W2 + (size_t)e * NH * ND;
    const float* Arow = g_H + (size_t)(row0 + lm) * NH + lk;  // slack rows are valid memory

    float acc[4][4];
#pragma unroll
    for (int i = 0; i < 4; i++)
#pragma unroll
        for (int j = 0; j < 4; j++) acc[i][j] = 0.f;

    for (int k0 = 0; k0 < NH; k0 += 16) {
        float4 av = *(const float4*)(Arow + k0);
        As[lk + 0][lm] = av.x; As[lk + 1][lm] = av.y;
        As[lk + 2][lm] = av.z; As[lk + 3][lm] = av.w;
        *(float4*)&Bs[bk][bn] =
            *(const float4*)(W2e + (size_t)(k0 + bk) * ND + n0 + bn);
        __syncthreads();
#pragma unroll
        for (int k = 0; k < 16; k++) {
            float4 a = *(const float4*)&As[k][ty];
            float4 b = *(const float4*)&Bs[k][tx];
            float a4[4] = {a.x, a.y, a.z, a.w};
            float b4[4] = {b.x, b.y, b.z, b.w};
#pragma unroll
            for (int i = 0; i < 4; i++)
#pragma unroll
                for (int j = 0; j < 4; j++)
                    acc[i][j] = fmaf(a4[i], b4[j], acc[i][j]);
        }
        __syncthreads();
    }

#pragma unroll
    for (int i = 0; i < 4; i++) {
        if (ty + i < valid) {
            size_t row = (size_t)(row0 + ty + i);
#pragma unroll
            for (int j = 0; j < 4; j++) {
                int col = n0 + tx + j;
                g_Y[row * ND + col] = acc[i][j] + b2[e * ND + col];
            }
        }
    }
}

// ---------------- combine: out[t] = w0*Y[s0] + w1*Y[s1] ----------------------
__global__ __launch_bounds__(256) void k_combine(float* __restrict__ out) {
    int idx = blockIdx.x * 256 + threadIdx.x;    // NT*ND/4 threads
    int t = idx >> 8;            // ND/4 = 256 float4 per token
    int c = (idx & 255) << 2;
    float w0 = g_topw[t * 2 + 0], w1 = g_topw[t * 2 + 1];
    int   s0 = g_slot[t * 2 + 0], s1 = g_slot[t * 2 + 1];
    float4 y0 = *(const float4*)&g_Y[(size_t)s0 * ND + c];
    float4 y1 = *(const float4*)&g_Y[(size_t)s1 * ND + c];
    float4 o;
    o.x = w0 * y0.x + w1 * y1.x;
    o.y = w0 * y0.y + w1 * y1.y;
    o.z = w0 * y0.z + w1 * y1.z;
    o.w = w0 * y0.w + w1 * y1.w;
    *(float4*)&out[(size_t)t * ND + c] = o;
}

// ---------------- launch -----------------------------------------------------
extern "C" void kernel_launch(void* const* d_in, const int* in_sizes, int n_in,
                              void* d_out, int out_size) {
    const float* x  = (const float*)d_in[0];
    const float* Wg = (const float*)d_in[1];
    const float* W1 = (const float*)d_in[2];
    const float* b1 = (const float*)d_in[3];
    const float* W2 = (const float*)d_in[4];
    const float* b2 = (const float*)d_in[5];
    float* out = (float*)d_out;

    k_init<<<1, 32>>>();
    k_router<<<NT / 8, 256>>>(x, Wg);
    k_scan<<<1, 32>>>(out, out_size);
    k_fill<<<NT / 256, 256>>>();
    k_gemm1<<<dim3(NT / 64, NH / 64, NE), 256>>>(x, W1, b1);
    k_gemm2<<<dim3(NT / 64, ND / 64, NE), 256>>>(W2, b2);
    k_combine<<<NT * ND / 4 / 256, 256>>>(out);
}